// round 1
// baseline (speedup 1.0000x reference)
#include <cuda_runtime.h>
#include <cuda_bf16.h>
#include <cstdint>

// Embedding gather: out[i, :] = embeddings[x[i], :]
// x: int32 [8192], embeddings: fp32 [32000, 1024], out: fp32 [8192, 1024]
//
// HBM-bound copy. One CTA per row, 256 threads x float4 = 4KB row.

static constexpr int EMBED_DIM = 1024;
static constexpr int VEC_PER_ROW = EMBED_DIM / 4;  // 256 float4 per row

__global__ __launch_bounds__(256, 8)
void embedding_gather_kernel(const int* __restrict__ idx,
                             const float4* __restrict__ emb,
                             float4* __restrict__ out)
{
    const int row = blockIdx.x;
    const int t = threadIdx.x;
    const long long src_row = (long long)idx[row];
    out[(long long)row * VEC_PER_ROW + t] = emb[src_row * VEC_PER_ROW + t];
}

extern "C" void kernel_launch(void* const* d_in, const int* in_sizes, int n_in,
                              void* d_out, int out_size)
{
    const int*   x   = (const int*)d_in[0];          // [4, 2048] int32 indices
    const float* emb = (const float*)d_in[1];        // [32000, 1024] fp32
    float*       out = (float*)d_out;                // [4, 2048, 1024] fp32

    const int n_rows = in_sizes[0];                  // 8192

    embedding_gather_kernel<<<n_rows, 256>>>(
        x, (const float4*)emb, (float4*)out);
}

// round 2
// speedup vs baseline: 1.1331x; 1.1331x over previous
#include <cuda_runtime.h>
#include <cuda_bf16.h>
#include <cstdint>

// Embedding gather: out[i, :] = embeddings[x[i], :]
// x: int32 [8192], embeddings: fp32 [32000, 1024], out: fp32 [8192, 1024]
//
// Latency-bound fix: 8 rows per CTA, each thread carries 8 independent
// float4 gathers in flight (MLP=8) before any store.

static constexpr int EMBED_DIM    = 1024;
static constexpr int VEC_PER_ROW  = EMBED_DIM / 4;   // 256 float4 per row
static constexpr int ROWS_PER_CTA = 8;

__global__ __launch_bounds__(256, 4)
void embedding_gather_kernel(const int* __restrict__ idx,
                             const float4* __restrict__ emb,
                             float4* __restrict__ out)
{
    const int  base = blockIdx.x * ROWS_PER_CTA;
    const int  t    = threadIdx.x;

    // 8 independent index loads (broadcast across CTA, mostly L2/L1 hits)
    long long src[ROWS_PER_CTA];
#pragma unroll
    for (int r = 0; r < ROWS_PER_CTA; r++)
        src[r] = (long long)idx[base + r];

    // 8 independent gathers — front-batched so ptxas issues them back-to-back
    float4 v[ROWS_PER_CTA];
#pragma unroll
    for (int r = 0; r < ROWS_PER_CTA; r++)
        v[r] = emb[src[r] * VEC_PER_ROW + t];

    // 8 coalesced stores
#pragma unroll
    for (int r = 0; r < ROWS_PER_CTA; r++)
        out[(long long)(base + r) * VEC_PER_ROW + t] = v[r];
}

extern "C" void kernel_launch(void* const* d_in, const int* in_sizes, int n_in,
                              void* d_out, int out_size)
{
    const int*   x   = (const int*)d_in[0];          // [4, 2048] int32 indices
    const float* emb = (const float*)d_in[1];        // [32000, 1024] fp32
    float*       out = (float*)d_out;                // [4, 2048, 1024] fp32

    const int n_rows = in_sizes[0];                  // 8192
    const int n_cta  = n_rows / ROWS_PER_CTA;        // 1024

    embedding_gather_kernel<<<n_cta, 256>>>(
        x, (const float4*)emb, (float4*)out);
}